// round 1
// baseline (speedup 1.0000x reference)
#include <cuda_runtime.h>
#include <cstdint>

// SigmaModel: h = relu([s,a] @ W1^T + b1); tri = h @ W2^T + b2;
// out[b,i,j] = tri[idx(min(i,j),max(i,j))], diag -> exp.
//
// B=131072, D=32, A=8, IN=40, H=64, TRI=528. Output float32 [B,32,32].

#define BATCH    131072
#define SDIM     32
#define ADIM     8
#define INDIM    40
#define HID      64
#define TRI      528
#define ROWS     64          // rows per CTA
#define NT       512         // threads per CTA
#define NPAD     578         // padded W2/tri row stride (floats); even, !=0 mod small pow2
#define NCOV     576         // covered (padded) tri columns = 32 lanes * 18 cols

// shared memory layout (float offsets)
#define SM_W2    0                      // [64][NPAD] = 36992 floats; reused as tri buffer [ROWS][NPAD]
#define SM_H     36992                  // [ROWS][64] = 4096
#define SM_X     41088                  // [ROWS][INDIM] = 2560
#define SM_W1    43648                  // [INDIM][64] transposed = 2560
#define SM_B1    46208                  // [64]
#define SM_B2    46272                  // [NCOV] = 576
#define SM_FLOATS 46848                 // 187392 bytes

// ---- packed f32x2 helpers (sm_103a) ----
__device__ __forceinline__ unsigned long long pack2(float lo, float hi) {
    unsigned long long r;
    asm("mov.b64 %0, {%1, %2};" : "=l"(r) : "f"(lo), "f"(hi));
    return r;
}
__device__ __forceinline__ void unpack2(unsigned long long v, float& lo, float& hi) {
    asm("mov.b64 {%0, %1}, %2;" : "=f"(lo), "=f"(hi) : "l"(v));
}
__device__ __forceinline__ void fma2(unsigned long long& d, unsigned long long a,
                                     unsigned long long b) {
    asm("fma.rn.f32x2 %0, %1, %2, %0;" : "+l"(d) : "l"(a), "l"(b));
}

__global__ void __launch_bounds__(NT, 1)
sigma_fused_kernel(const float* __restrict__ s,
                   const float* __restrict__ a,
                   const float* __restrict__ W1,
                   const float* __restrict__ b1,
                   const float* __restrict__ W2,
                   const float* __restrict__ b2,
                   float* __restrict__ out) {
    extern __shared__ float smem[];
    float* sW2 = smem + SM_W2;   // [k][n] transposed, stride NPAD (aliased later as tri buf)
    float* sH  = smem + SM_H;    // [row][k]
    float* sX  = smem + SM_X;    // [row][INDIM]
    float* sW1 = smem + SM_W1;   // [k][hh] transposed
    float* sB1 = smem + SM_B1;
    float* sB2 = smem + SM_B2;

    const int tid  = threadIdx.x;
    const int row0 = blockIdx.x * ROWS;

    // ---------------- Phase 0: stage everything into smem ----------------
    // s -> sX[:, 0:32]   (coalesced global read)
    for (int idx = tid; idx < ROWS * SDIM; idx += NT) {
        int r = idx >> 5, c = idx & 31;
        sX[r * INDIM + c] = s[(size_t)row0 * SDIM + idx];
    }
    // a -> sX[:, 32:40]
    for (int idx = tid; idx < ROWS * ADIM; idx += NT) {
        int r = idx >> 3, c = idx & 7;
        sX[r * INDIM + SDIM + c] = a[(size_t)row0 * ADIM + idx];
    }
    // W1[hh][k] -> sW1[k][hh]
    for (int idx = tid; idx < HID * INDIM; idx += NT) {
        int hh = idx / INDIM, k = idx - hh * INDIM;
        sW1[k * HID + hh] = W1[idx];
    }
    if (tid < HID) sB1[tid] = b1[tid];
    for (int idx = tid; idx < NCOV; idx += NT)
        sB2[idx] = (idx < TRI) ? b2[idx] : 0.0f;
    // W2 zero-pad columns [TRI, NPAD)
    for (int idx = tid; idx < HID * (NPAD - TRI); idx += NT) {
        int k = idx / (NPAD - TRI), t = TRI + (idx - k * (NPAD - TRI));
        sW2[k * NPAD + t] = 0.0f;
    }
    // W2[t][k] -> sW2[k][t]  (coalesced global read; ~2-way STS conflict)
    for (int idx = tid; idx < TRI * HID; idx += NT) {
        int t = idx >> 6, k = idx & 63;
        sW2[k * NPAD + t] = W2[idx];
    }
    __syncthreads();

    // ---------------- Phase 1: H = relu(X @ W1^T + b1) ----------------
    {
        const int hr = tid >> 3;           // row 0..63
        const int hg = (tid & 7) * 8;      // hidden group of 8
        float acc[8];
#pragma unroll
        for (int u = 0; u < 8; ++u) acc[u] = sB1[hg + u];
        const float* xrow = &sX[hr * INDIM];
#pragma unroll 4
        for (int k = 0; k < INDIM; ++k) {
            float xv = xrow[k];
            const float4 w0 = *reinterpret_cast<const float4*>(&sW1[k * HID + hg]);
            const float4 w1 = *reinterpret_cast<const float4*>(&sW1[k * HID + hg + 4]);
            acc[0] = fmaf(xv, w0.x, acc[0]);
            acc[1] = fmaf(xv, w0.y, acc[1]);
            acc[2] = fmaf(xv, w0.z, acc[2]);
            acc[3] = fmaf(xv, w0.w, acc[3]);
            acc[4] = fmaf(xv, w1.x, acc[4]);
            acc[5] = fmaf(xv, w1.y, acc[5]);
            acc[6] = fmaf(xv, w1.z, acc[6]);
            acc[7] = fmaf(xv, w1.w, acc[7]);
        }
#pragma unroll
        for (int u = 0; u < 8; ++u)
            sH[hr * HID + hg + u] = fmaxf(acc[u], 0.0f);
    }
    __syncthreads();

    // ---------------- Phase 2: tri = H @ W2^T + b2 (f32x2 GEMM) ----------------
    // 512 threads = 16 row-groups (ty) x 32 col-groups (tx).
    // Thread tile: 4 rows x 9 column-pairs; pair columns are (2*tx + 64*u, +1).
    const int tx = tid & 31;
    const int ty = tid >> 5;
    const int r0 = ty * 4;

    unsigned long long acc2[4][9];
#pragma unroll
    for (int r = 0; r < 4; ++r)
#pragma unroll
        for (int u = 0; u < 9; ++u) acc2[r][u] = 0ULL;  // bits of (0.0f, 0.0f)

    const int cbase = 2 * tx;
#pragma unroll 4
    for (int k = 0; k < HID; ++k) {
        unsigned long long hb[4];
#pragma unroll
        for (int r = 0; r < 4; ++r) {
            float hv = sH[(r0 + r) * HID + k];   // warp-broadcast LDS
            hb[r] = pack2(hv, hv);
        }
        const float* wrow = &sW2[k * NPAD + cbase];
#pragma unroll
        for (int u = 0; u < 9; ++u) {
            unsigned long long w =
                *reinterpret_cast<const unsigned long long*>(wrow + 64 * u);  // LDS.64
#pragma unroll
            for (int r = 0; r < 4; ++r) fma2(acc2[r][u], hb[r], w);
        }
    }

    // All GEMM reads of sW2 must complete before we alias it as the tri buffer.
    __syncthreads();
    float* sTri = sW2;  // [ROWS][NPAD]
#pragma unroll
    for (int u = 0; u < 9; ++u) {
        const int c = cbase + 64 * u;
        const float blo = sB2[c], bhi = sB2[c + 1];
#pragma unroll
        for (int r = 0; r < 4; ++r) {
            float lo, hi;
            unpack2(acc2[r][u], lo, hi);
            *reinterpret_cast<float2*>(&sTri[(r0 + r) * NPAD + c]) =
                make_float2(lo + blo, hi + bhi);
        }
    }
    __syncthreads();

    // ---------------- Phase 3: scatter to symmetrized 32x32, exp diag ----------------
    // out element (row, i, j) = tri[idx(min,max)]; idx(i,j) = 32i - i(i+1)/2 + j.
    float4* out4 = reinterpret_cast<float4*>(out + (size_t)row0 * 1024);
    for (int idx = tid; idx < ROWS * 256; idx += NT) {
        const int r  = idx >> 8;         // row within block
        const int o4 = idx & 255;        // quad within 1024-wide output row
        const int i  = o4 >> 3;          // (o4*4) / 32
        const int j0 = (o4 & 7) * 4;
        const float* tr = &sTri[r * NPAD];
        float vals[4];
#pragma unroll
        for (int e = 0; e < 4; ++e) {
            const int j  = j0 + e;
            const int ii = (i < j) ? i : j;
            const int jj = (i < j) ? j : i;
            const int t  = ii * 32 - ((ii * (ii + 1)) >> 1) + jj;
            float v = tr[t];
            if (i == j) v = expf(v);
            vals[e] = v;
        }
        out4[idx] = make_float4(vals[0], vals[1], vals[2], vals[3]);
    }
}

extern "C" void kernel_launch(void* const* d_in, const int* in_sizes, int n_in,
                              void* d_out, int out_size) {
    (void)in_sizes; (void)n_in; (void)out_size;
    const float* s  = (const float*)d_in[0];
    const float* a  = (const float*)d_in[1];
    const float* W1 = (const float*)d_in[2];
    const float* b1 = (const float*)d_in[3];
    const float* W2 = (const float*)d_in[4];
    const float* b2 = (const float*)d_in[5];
    float* out = (float*)d_out;

    const size_t smem_bytes = SM_FLOATS * sizeof(float);  // 187392
    cudaFuncSetAttribute(sigma_fused_kernel,
                         cudaFuncAttributeMaxDynamicSharedMemorySize,
                         (int)smem_bytes);

    const int grid = BATCH / ROWS;  // 2048
    sigma_fused_kernel<<<grid, NT, smem_bytes>>>(s, a, W1, b1, W2, b2, out);
}

// round 3
// speedup vs baseline: 1.1064x; 1.1064x over previous
#include <cuda_runtime.h>
#include <cstdint>

// SigmaModel: h = relu([s,a] @ W1^T + b1); tri = h @ W2^T + b2;
// out[b,i,j] = tri[t(min(i,j),max(i,j))], diag -> exp.
// B=131072, IN=40, H=64, TRI=528. Output float32 [B,32,32].
// Scalar f32x2-FMA design (tcgen05 unavailable: harness emits compute_103 PTX).

#define BATCH    131072
#define SDIM     32
#define ADIM     8
#define INDIM    40
#define HID      64
#define TRI      528
#define ROWS     64          // batch rows per CTA
#define NT       512
#define NPAD     578         // W2/tri row stride (floats): even; %32==2 -> 2-way STS max
#define NCOV     576         // covered tri columns (padded with zeros)

// shared memory layout (float offsets)
#define SM_W2    0           // [64][NPAD] = 36992 floats; aliased as tri buffer after GEMM
#define SM_H     36992       // [ROWS][64]
#define SM_X     41088       // [ROWS][INDIM]
#define SM_W1    43648       // [INDIM][64] transposed
#define SM_B1    46208       // [64]
#define SM_B2    46272       // [NCOV]
#define SM_TBL   46848       // int[1024]: t | (diag<<16)
#define SM_FLOATS 47872      // 191488 bytes

// ---- packed f32x2 helpers (sm_103a) ----
__device__ __forceinline__ unsigned long long pack2(float lo, float hi) {
    unsigned long long r;
    asm("mov.b64 %0, {%1, %2};" : "=l"(r) : "f"(lo), "f"(hi));
    return r;
}
__device__ __forceinline__ void unpack2(unsigned long long v, float& lo, float& hi) {
    asm("mov.b64 {%0, %1}, %2;" : "=f"(lo), "=f"(hi) : "l"(v));
}
__device__ __forceinline__ void fma2(unsigned long long& d, unsigned long long a,
                                     unsigned long long b) {
    asm("fma.rn.f32x2 %0, %1, %2, %0;" : "+l"(d) : "l"(a), "l"(b));
}

__global__ void __launch_bounds__(NT, 1)
sigma_fused_kernel(const float* __restrict__ s,
                   const float* __restrict__ a,
                   const float* __restrict__ W1,
                   const float* __restrict__ b1,
                   const float* __restrict__ W2,
                   const float* __restrict__ b2,
                   float* __restrict__ out) {
    extern __shared__ float smem[];
    float* sW2 = smem + SM_W2;
    float* sH  = smem + SM_H;
    float* sX  = smem + SM_X;
    float* sW1 = smem + SM_W1;
    float* sB1 = smem + SM_B1;
    float* sB2 = smem + SM_B2;
    int*   sTbl = (int*)(smem + SM_TBL);

    const int tid  = threadIdx.x;
    const int row0 = blockIdx.x * ROWS;

    // ---------------- Phase 0: staging (W2 first: it is the long pole) ------
    // W2[t][k] -> sW2[k][t] (coalesced LDG.32; STS 2-way conflict max)
    for (int idx = tid; idx < TRI * HID; idx += NT) {
        int t = idx >> 6, k = idx & 63;
        sW2[k * NPAD + t] = W2[idx];
    }
    // zero-pad W2 columns [TRI, NPAD)
    for (int idx = tid; idx < HID * (NPAD - TRI); idx += NT) {
        int k = idx / (NPAD - TRI), t = TRI + (idx - k * (NPAD - TRI));
        sW2[k * NPAD + t] = 0.0f;
    }
    // s -> sX[:, 0:32]
    for (int idx = tid; idx < ROWS * SDIM; idx += NT) {
        int r = idx >> 5, c = idx & 31;
        sX[r * INDIM + c] = s[(size_t)row0 * SDIM + idx];
    }
    // a -> sX[:, 32:40]
    for (int idx = tid; idx < ROWS * ADIM; idx += NT) {
        int r = idx >> 3, c = idx & 7;
        sX[r * INDIM + SDIM + c] = a[(size_t)row0 * ADIM + idx];
    }
    // W1[hh][k] -> sW1[k][hh]
    for (int idx = tid; idx < HID * INDIM; idx += NT) {
        int hh = idx / INDIM, k = idx - hh * INDIM;
        sW1[k * HID + hh] = W1[idx];
    }
    if (tid < HID) sB1[tid] = b1[tid];
    for (int idx = tid; idx < NCOV; idx += NT)
        sB2[idx] = (idx < TRI) ? b2[idx] : 0.0f;
    // scatter index table: out flat o=(i,j) -> tri index + diag flag
    for (int o = tid; o < 1024; o += NT) {
        int i = o >> 5, j = o & 31;
        int ii = (i < j) ? i : j;
        int jj = (i < j) ? j : i;
        int t = ii * 32 - ((ii * (ii + 1)) >> 1) + jj;
        sTbl[o] = t | ((i == j) ? (1 << 16) : 0);
    }
    __syncthreads();

    // ---------------- Phase 1: H = relu(X @ W1^T + b1) ----------------------
    {
        const int hr = tid >> 3;           // row 0..63
        const int hg = (tid & 7) * 8;      // 8 hidden cols
        float acc[8];
#pragma unroll
        for (int u = 0; u < 8; ++u) acc[u] = sB1[hg + u];
        const float* xrow = &sX[hr * INDIM];
#pragma unroll 5
        for (int k = 0; k < INDIM; ++k) {
            float xv = xrow[k];
            const float4 w0 = *reinterpret_cast<const float4*>(&sW1[k * HID + hg]);
            const float4 w1 = *reinterpret_cast<const float4*>(&sW1[k * HID + hg + 4]);
            acc[0] = fmaf(xv, w0.x, acc[0]);
            acc[1] = fmaf(xv, w0.y, acc[1]);
            acc[2] = fmaf(xv, w0.z, acc[2]);
            acc[3] = fmaf(xv, w0.w, acc[3]);
            acc[4] = fmaf(xv, w1.x, acc[4]);
            acc[5] = fmaf(xv, w1.y, acc[5]);
            acc[6] = fmaf(xv, w1.z, acc[6]);
            acc[7] = fmaf(xv, w1.w, acc[7]);
        }
#pragma unroll
        for (int u = 0; u < 8; ++u)
            sH[hr * HID + hg + u] = fmaxf(acc[u], 0.0f);
    }
    __syncthreads();

    // ---------------- Phase 2: tri = H @ W2^T + b2 (f32x2 GEMM) -------------
    // 16 row-groups (ty) x 32 lanes (tx); thread tile 4 rows x 9 col-pairs.
    const int tx = tid & 31;
    const int ty = tid >> 5;
    const int r0 = ty * 4;
    const int cbase = 2 * tx;

    unsigned long long acc2[4][9];
#pragma unroll
    for (int u = 0; u < 9; ++u) {
        const int c = cbase + 64 * u;
        unsigned long long bini = pack2(sB2[c], sB2[c + 1]);
#pragma unroll
        for (int r = 0; r < 4; ++r) acc2[r][u] = bini;
    }

#pragma unroll 4
    for (int k = 0; k < HID; ++k) {
        // issue ALL loads first (13 independent LDS), then the 36 FFMA2s
        const float* wrow = &sW2[k * NPAD + cbase];
        unsigned long long w[9];
#pragma unroll
        for (int u = 0; u < 9; ++u)
            w[u] = *reinterpret_cast<const unsigned long long*>(wrow + 64 * u);
        unsigned long long hb[4];
#pragma unroll
        for (int r = 0; r < 4; ++r) {
            float hv = sH[(r0 + r) * HID + k];   // warp-broadcast LDS
            hb[r] = pack2(hv, hv);
        }
#pragma unroll
        for (int u = 0; u < 9; ++u)
#pragma unroll
            for (int r = 0; r < 4; ++r) fma2(acc2[r][u], hb[r], w[u]);
    }

    // all GEMM reads of sW2 done before aliasing it as the tri buffer
    __syncthreads();
    float* sTri = sW2;  // [ROWS][NPAD]
#pragma unroll
    for (int u = 0; u < 9; ++u) {
        const int c = cbase + 64 * u;
#pragma unroll
        for (int r = 0; r < 4; ++r) {
            float lo, hi;
            unpack2(acc2[r][u], lo, hi);
            *reinterpret_cast<float2*>(&sTri[(r0 + r) * NPAD + c]) = make_float2(lo, hi);
        }
    }
    __syncthreads();

    // ---------------- Phase 3: scatter to symmetrized 32x32, exp diag -------
    const int4* tbl4 = reinterpret_cast<const int4*>(sTbl);
    float4* out4 = reinterpret_cast<float4*>(out + (size_t)row0 * 1024);
    for (int idx = tid; idx < ROWS * 256; idx += NT) {
        const int r  = idx >> 8;
        const int o4 = idx & 255;
        const int4 tt = tbl4[o4];
        const float* tr = &sTri[r * NPAD];
        float v0 = tr[tt.x & 0xffff];
        float v1 = tr[tt.y & 0xffff];
        float v2 = tr[tt.z & 0xffff];
        float v3 = tr[tt.w & 0xffff];
        if (tt.x >> 16) v0 = __expf(v0);
        if (tt.y >> 16) v1 = __expf(v1);
        if (tt.z >> 16) v2 = __expf(v2);
        if (tt.w >> 16) v3 = __expf(v3);
        out4[idx] = make_float4(v0, v1, v2, v3);
    }
}

extern "C" void kernel_launch(void* const* d_in, const int* in_sizes, int n_in,
                              void* d_out, int out_size) {
    (void)in_sizes; (void)n_in; (void)out_size;
    const float* s  = (const float*)d_in[0];
    const float* a  = (const float*)d_in[1];
    const float* W1 = (const float*)d_in[2];
    const float* b1 = (const float*)d_in[3];
    const float* W2 = (const float*)d_in[4];
    const float* b2 = (const float*)d_in[5];
    float* out = (float*)d_out;

    const size_t smem_bytes = SM_FLOATS * sizeof(float);  // 191488
    cudaFuncSetAttribute(sigma_fused_kernel,
                         cudaFuncAttributeMaxDynamicSharedMemorySize,
                         (int)smem_bytes);
    sigma_fused_kernel<<<BATCH / ROWS, NT, smem_bytes>>>(s, a, W1, b1, W2, b2, out);
}